// round 4
// baseline (speedup 1.0000x reference)
#include <cuda_runtime.h>
#include <cuda_bf16.h>
#include <cstdint>
#include <cstddef>

// Problem constants
#define BB   64
#define CIN  2048
#define PP   512
#define NN   196      // H*W = 14*14
#define HH   14
#define QKV3 1536     // 3*P
#define COUT 2048     // P*EXP

// ---------------------------------------------------------------------------
// Scratch buffers (static device globals: allocation APIs are forbidden)
// ---------------------------------------------------------------------------
__device__ float g_out1[(size_t)BB * PP * NN];
__device__ float g_qkv [(size_t)BB * QKV3 * NN];
__device__ float g_attn[(size_t)BB * NN * NN];
__device__ float g_aout[(size_t)BB * PP * NN];
__device__ float g_pos [(size_t)PP * NN];

// ---------------------------------------------------------------------------
// Packed fp32x2 FMA (sm_103a FFMA2; PTX-only, ptxas never auto-fuses)
// ---------------------------------------------------------------------------
__device__ __forceinline__ unsigned long long ffma2(unsigned long long a,
                                                    unsigned long long b,
                                                    unsigned long long c) {
    unsigned long long d;
    asm("fma.rn.f32x2 %0, %1, %2, %3;" : "=l"(d) : "l"(a), "l"(b), "l"(c));
    return d;
}

// ---------------------------------------------------------------------------
// pos[c][n] = rel_h[c][h] + rel_w[c][w],  n = h*14 + w
// ---------------------------------------------------------------------------
__global__ void posprep_kernel(const float* __restrict__ rh,
                               const float* __restrict__ rw,
                               float* __restrict__ pos) {
    int i = blockIdx.x * blockDim.x + threadIdx.x;
    if (i < PP * NN) {
        int c = i / NN, n = i % NN;
        pos[i] = rh[c * HH + n / HH] + rw[c * HH + n % HH];
    }
}

// ---------------------------------------------------------------------------
// Generic GEMM:  C[b][m][n] = sum_k A[m][k] * B[b][k][n]    (n = 0..195)
//   A row-major [M,K] (per-batch via aStride; 0 = shared weights)
//   B [K,196] n-contiguous, or TRANS_B: B[b] = attn[196(n),196(k)], consume
//   B[k][n] = attn[n][k].
//   MODE 0: plain   MODE 1: BN+ReLU   MODE 2: BN + residual + ReLU
// Tile BM=128 x BN=196, BK=16, 224 threads, per-thread 8 rows x 14 cols,
// 7 packed f32x2 accumulators per row (56 FFMA2 / 15 LDS.64 per k-step).
// A tile pre-duplicated as float2(a,a) so the broadcast is a single LDS.64.
// Double-buffered: loads for tile i+1 issue before compute of tile i.
// ---------------------------------------------------------------------------
template<int MODE, bool TRANS_B>
__global__ void __launch_bounds__(224)
gemm196_kernel(const float* __restrict__ A, size_t aStride,
               const float* __restrict__ B, size_t bStride,
               float* __restrict__ C, size_t cStride,
               int M, int K,
               const float* __restrict__ gg, const float* __restrict__ bbeta,
               const float* __restrict__ mmu, const float* __restrict__ vvar,
               const float* __restrict__ res, size_t resStride)
{
    __shared__ float2 As2[2][16][129];  // pad 129: conflict-free phases
    __shared__ float  Bs[2][16][196];

    const int batch = blockIdx.y;
    const int m0    = blockIdx.x * 128;
    const float* Ab = A + (size_t)batch * aStride;
    const float* Bb = B + (size_t)batch * bStride;

    const int tid = threadIdx.x;
    const int tx  = tid % 14;   // cols tx*14 .. tx*14+13
    const int ty  = tid / 14;   // rows ty*8 .. ty*8+7

    unsigned long long acc[8][7];
    #pragma unroll
    for (int i = 0; i < 8; i++)
        #pragma unroll
        for (int j = 0; j < 7; j++) acc[i][j] = 0ull;

    // ---- tile loader (LDG + STS into buffer `buf` for k-offset k0) ----
    auto load_tile = [&](int buf, int k0) {
        // A tile (duplicated pair): As2[buf][kk][r] = {a, a}   (16 x 128)
        for (int idx = tid; idx < 2048; idx += 224) {
            int r = idx >> 4, kk = idx & 15;
            int kc = k0 + kk;
            float a = (kc < K) ? Ab[(size_t)(m0 + r) * K + kc] : 0.f;
            As2[buf][kk][r] = make_float2(a, a);
        }
        if (!TRANS_B) {
            for (int i = tid; i < 784; i += 224) {       // 16 * 49 float4
                int kk = i / 49, n4 = i % 49;
                int kc = k0 + kk;
                float4 v4 = make_float4(0.f, 0.f, 0.f, 0.f);
                if (kc < K) v4 = *(const float4*)(Bb + (size_t)kc * NN + n4 * 4);
                *(float4*)&Bs[buf][kk][n4 * 4] = v4;
            }
        } else {
            if (tid < NN) {
                const float* row = Bb + (size_t)tid * NN + k0;  // attn[n=tid][k0..]
                #pragma unroll
                for (int q4 = 0; q4 < 4; q4++) {
                    float4 v4;
                    int kc = k0 + q4 * 4;
                    if (kc + 3 < K) {
                        v4 = *(const float4*)(row + q4 * 4);
                    } else {
                        v4.x = (kc + 0 < K) ? row[q4 * 4 + 0] : 0.f;
                        v4.y = (kc + 1 < K) ? row[q4 * 4 + 1] : 0.f;
                        v4.z = (kc + 2 < K) ? row[q4 * 4 + 2] : 0.f;
                        v4.w = (kc + 3 < K) ? row[q4 * 4 + 3] : 0.f;
                    }
                    Bs[buf][q4 * 4 + 0][tid] = v4.x;
                    Bs[buf][q4 * 4 + 1][tid] = v4.y;
                    Bs[buf][q4 * 4 + 2][tid] = v4.z;
                    Bs[buf][q4 * 4 + 3][tid] = v4.w;
                }
            }
        }
    };

    auto compute_tile = [&](int buf) {
        #pragma unroll
        for (int kk = 0; kk < 16; kk++) {
            unsigned long long a2[8], b2[7];
            #pragma unroll
            for (int i = 0; i < 8; i++)
                a2[i] = *(const unsigned long long*)&As2[buf][kk][ty * 8 + i];
            #pragma unroll
            for (int j = 0; j < 7; j++)
                b2[j] = *(const unsigned long long*)&Bs[buf][kk][tx * 14 + 2 * j];
            #pragma unroll
            for (int i = 0; i < 8; i++)
                #pragma unroll
                for (int j = 0; j < 7; j++)
                    acc[i][j] = ffma2(a2[i], b2[j], acc[i][j]);
        }
    };

    // ---- software pipeline ----
    load_tile(0, 0);
    __syncthreads();
    int cur = 0;
    for (int k0 = 16; k0 < K; k0 += 16) {
        load_tile(cur ^ 1, k0);   // LDG latency overlaps compute below
        compute_tile(cur);
        __syncthreads();          // next buffer visible; cur free for reuse
        cur ^= 1;
    }
    compute_tile(cur);

    // Epilogue
    float* Cb = C + (size_t)batch * cStride;
    #pragma unroll
    for (int i = 0; i < 8; i++) {
        int m = m0 + ty * 8 + i;
        float s = 1.f, t = 0.f;
        if (MODE >= 1) {
            s = gg[m] * rsqrtf(vvar[m] + 1e-5f);
            t = bbeta[m] - mmu[m] * s;
        }
        const float* rb = (MODE == 2)
            ? (res + (size_t)batch * resStride + (size_t)m * NN) : nullptr;
        #pragma unroll
        for (int j = 0; j < 7; j++) {
            int n = tx * 14 + 2 * j;
            float v0 = __uint_as_float((unsigned int)(acc[i][j]));
            float v1 = __uint_as_float((unsigned int)(acc[i][j] >> 32));
            if (MODE >= 1) { v0 = v0 * s + t; v1 = v1 * s + t; }
            if (MODE == 2) {
                float2 r2 = *(const float2*)&rb[n];
                v0 += r2.x; v1 += r2.y;
            }
            if (MODE >= 1) { v0 = fmaxf(v0, 0.f); v1 = fmaxf(v1, 0.f); }
            float2 o; o.x = v0; o.y = v1;
            *(float2*)&Cb[(size_t)m * NN + n] = o;
        }
    }
}

// ---------------------------------------------------------------------------
// Attention logits: L[b][n][m] = sum_c q[c][n]*k[c][m] + sum_c pos[c][n]*q[c][m]
// Single K=1024 GEMM: A = concat(q,pos) (col n), B = concat(k,q) (col m).
// Tile 64(n) x 196(m); n rows predicated (196 = 3*64 + 4). Double-buffered.
// ---------------------------------------------------------------------------
__global__ void __launch_bounds__(224, 2)
logits_kernel(const float* __restrict__ qkv, const float* __restrict__ pos,
              float* __restrict__ Lout)
{
    __shared__ float2 As2[2][16][65];
    __shared__ float  Bs[2][16][196];

    const int batch = blockIdx.y;
    const int n0    = blockIdx.x * 64;
    const float* qb = qkv + (size_t)batch * ((size_t)QKV3 * NN);
    const float* kb = qb + (size_t)PP * NN;

    const int tid = threadIdx.x;
    const int tx  = tid % 14, ty = tid / 14;

    unsigned long long acc[4][7];
    #pragma unroll
    for (int i = 0; i < 4; i++)
        #pragma unroll
        for (int j = 0; j < 7; j++) acc[i][j] = 0ull;

    auto load_tile = [&](int buf, int k0) {
        for (int idx = tid; idx < 1024; idx += 224) {   // 16 x 64
            int kk = idx >> 6, r = idx & 63;
            int kc = k0 + kk;
            const float* arow = (kc < PP) ? (qb + (size_t)kc * NN)
                                          : (pos + (size_t)(kc - PP) * NN);
            int n = n0 + r;
            float a = (n < NN) ? arow[n] : 0.f;
            As2[buf][kk][r] = make_float2(a, a);
        }
        for (int i = tid; i < 784; i += 224) {
            int kk = i / 49, n4 = i % 49;
            int kc = k0 + kk;
            const float* brow = (kc < PP) ? (kb + (size_t)kc * NN)
                                          : (qb + (size_t)(kc - PP) * NN);
            *(float4*)&Bs[buf][kk][n4 * 4] = *(const float4*)(brow + n4 * 4);
        }
    };

    auto compute_tile = [&](int buf) {
        #pragma unroll
        for (int kk = 0; kk < 16; kk++) {
            unsigned long long a2[4], b2[7];
            #pragma unroll
            for (int i = 0; i < 4; i++)
                a2[i] = *(const unsigned long long*)&As2[buf][kk][ty * 4 + i];
            #pragma unroll
            for (int j = 0; j < 7; j++)
                b2[j] = *(const unsigned long long*)&Bs[buf][kk][tx * 14 + 2 * j];
            #pragma unroll
            for (int i = 0; i < 4; i++)
                #pragma unroll
                for (int j = 0; j < 7; j++)
                    acc[i][j] = ffma2(a2[i], b2[j], acc[i][j]);
        }
    };

    load_tile(0, 0);
    __syncthreads();
    int cur = 0;
    for (int k0 = 16; k0 < 2 * PP; k0 += 16) {
        load_tile(cur ^ 1, k0);
        compute_tile(cur);
        __syncthreads();
        cur ^= 1;
    }
    compute_tile(cur);

    float* Lb = Lout + (size_t)batch * (NN * NN);
    #pragma unroll
    for (int i = 0; i < 4; i++) {
        int n = n0 + ty * 4 + i;
        if (n < NN) {
            #pragma unroll
            for (int j = 0; j < 7; j++) {
                int m = tx * 14 + 2 * j;
                float2 o;
                o.x = __uint_as_float((unsigned int)(acc[i][j]));
                o.y = __uint_as_float((unsigned int)(acc[i][j] >> 32));
                *(float2*)&Lb[(size_t)n * NN + m] = o;
            }
        }
    }
}

// ---------------------------------------------------------------------------
// In-place softmax over last dim (196). One warp per row; 7 elems/lane.
// ---------------------------------------------------------------------------
__global__ void softmax_kernel(float* __restrict__ L)
{
    int gw   = (blockIdx.x * blockDim.x + threadIdx.x) >> 5;
    int lane = threadIdx.x & 31;
    if (gw >= BB * NN) return;
    float* row = L + (size_t)gw * NN;

    float v[7];
    float mx = -1e30f;
    #pragma unroll
    for (int i = 0; i < 7; i++) {
        int m = lane + 32 * i;
        v[i] = (m < NN) ? row[m] : -1e30f;
        mx = fmaxf(mx, v[i]);
    }
    #pragma unroll
    for (int off = 16; off; off >>= 1)
        mx = fmaxf(mx, __shfl_xor_sync(0xffffffffu, mx, off));

    float sum = 0.f;
    #pragma unroll
    for (int i = 0; i < 7; i++) { v[i] = __expf(v[i] - mx); sum += v[i]; }
    #pragma unroll
    for (int off = 16; off; off >>= 1)
        sum += __shfl_xor_sync(0xffffffffu, sum, off);

    float inv = 1.f / sum;
    #pragma unroll
    for (int i = 0; i < 7; i++) {
        int m = lane + 32 * i;
        if (m < NN) row[m] = v[i] * inv;
    }
}

// ---------------------------------------------------------------------------
// Launch
// ---------------------------------------------------------------------------
extern "C" void kernel_launch(void* const* d_in, const int* in_sizes, int n_in,
                              void* d_out, int out_size)
{
    const float* x     = (const float*)d_in[0];
    const float* w1    = (const float*)d_in[1];
    const float* g1    = (const float*)d_in[2];
    const float* b1    = (const float*)d_in[3];
    const float* m1    = (const float*)d_in[4];
    const float* v1    = (const float*)d_in[5];
    const float* wqkv  = (const float*)d_in[6];
    const float* rel_h = (const float*)d_in[7];
    const float* rel_w = (const float*)d_in[8];
    const float* g2    = (const float*)d_in[9];
    const float* b2    = (const float*)d_in[10];
    const float* m2    = (const float*)d_in[11];
    const float* v2    = (const float*)d_in[12];
    const float* w3    = (const float*)d_in[13];
    const float* g3    = (const float*)d_in[14];
    const float* b3    = (const float*)d_in[15];
    const float* m3    = (const float*)d_in[16];
    const float* v3    = (const float*)d_in[17];
    float* out = (float*)d_out;

    float *p_out1, *p_qkv, *p_attn, *p_aout, *p_pos;
    cudaGetSymbolAddress((void**)&p_out1, g_out1);
    cudaGetSymbolAddress((void**)&p_qkv,  g_qkv);
    cudaGetSymbolAddress((void**)&p_attn, g_attn);
    cudaGetSymbolAddress((void**)&p_aout, g_aout);
    cudaGetSymbolAddress((void**)&p_pos,  g_pos);

    // pos[c][n] = rel_h + rel_w
    posprep_kernel<<<(PP * NN + 255) / 256, 256>>>(rel_h, rel_w, p_pos);

    // Stage 1: out1 = relu(bn1(w1 @ x))
    gemm196_kernel<1, false><<<dim3(PP / 128, BB), 224>>>(
        w1, 0, x, (size_t)CIN * NN, p_out1, (size_t)PP * NN,
        PP, CIN, g1, b1, m1, v1, nullptr, 0);

    // Stage 2: qkv = wqkv @ out1
    gemm196_kernel<0, false><<<dim3(QKV3 / 128, BB), 224>>>(
        wqkv, 0, p_out1, (size_t)PP * NN, p_qkv, (size_t)QKV3 * NN,
        QKV3, PP, nullptr, nullptr, nullptr, nullptr, nullptr, 0);

    // Stage 3: logits = Q^T K + Pos^T Q  (fused K=1024 GEMM)
    logits_kernel<<<dim3(4, BB), 224>>>(p_qkv, p_pos, p_attn);

    // Stage 4: softmax over m
    softmax_kernel<<<(BB * NN) / 8, 256>>>(p_attn);

    // Stage 5: aout = relu(bn2(V @ Attn^T))
    gemm196_kernel<1, true><<<dim3(PP / 128, BB), 224>>>(
        p_qkv + (size_t)2 * PP * NN, (size_t)QKV3 * NN,
        p_attn, (size_t)NN * NN, p_aout, (size_t)PP * NN,
        PP, NN, g2, b2, m2, v2, nullptr, 0);

    // Stage 6: out = relu(bn3(w3 @ aout) + x)
    gemm196_kernel<2, false><<<dim3(COUT / 128, BB), 224>>>(
        w3, 0, p_aout, (size_t)PP * NN, out, (size_t)COUT * NN,
        COUT, PP, g3, b3, m3, v3, x, (size_t)COUT * NN);
}

// round 12
// speedup vs baseline: 1.8492x; 1.8492x over previous
#include <cuda_runtime.h>
#include <cuda_bf16.h>
#include <cstdint>
#include <cstddef>

// Problem constants
#define BB   64
#define CIN  2048
#define PP   512
#define NN   196      // H*W = 14*14
#define HH   14
#define QKV3 1536     // 3*P
#define COUT 2048     // P*EXP

// ---------------------------------------------------------------------------
// Scratch buffers (static device globals: allocation APIs are forbidden)
// ---------------------------------------------------------------------------
__device__ float g_out1[(size_t)BB * PP * NN];
__device__ float g_qkv [(size_t)BB * QKV3 * NN];
__device__ float g_attn[(size_t)BB * NN * NN];
__device__ float g_aout[(size_t)BB * PP * NN];
__device__ float g_pos [(size_t)PP * NN];

// ---------------------------------------------------------------------------
// Packed fp32x2 FMA (used by the fp32 logits / AV kernels)
// ---------------------------------------------------------------------------
__device__ __forceinline__ unsigned long long ffma2(unsigned long long a,
                                                    unsigned long long b,
                                                    unsigned long long c) {
    unsigned long long d;
    asm("fma.rn.f32x2 %0, %1, %2, %3;" : "=l"(d) : "l"(a), "l"(b), "l"(c));
    return d;
}

// tf32 helpers
__device__ __forceinline__ unsigned f2tf32(float x) {
    unsigned u;
    asm("cvt.rna.tf32.f32 %0, %1;" : "=r"(u) : "f"(x));
    return u;
}
__device__ __forceinline__ void mma_tf32(float* d, const unsigned* a,
                                         const unsigned* b) {
    asm volatile(
        "mma.sync.aligned.m16n8k8.row.col.f32.tf32.tf32.f32 "
        "{%0,%1,%2,%3}, {%4,%5,%6,%7}, {%8,%9}, {%0,%1,%2,%3};"
        : "+f"(d[0]), "+f"(d[1]), "+f"(d[2]), "+f"(d[3])
        : "r"(a[0]), "r"(a[1]), "r"(a[2]), "r"(a[3]),
          "r"(b[0]), "r"(b[1]));
}

// ---------------------------------------------------------------------------
// pos[c][n] = rel_h[c][h] + rel_w[c][w],  n = h*14 + w
// ---------------------------------------------------------------------------
__global__ void posprep_kernel(const float* __restrict__ rh,
                               const float* __restrict__ rw,
                               float* __restrict__ pos) {
    int i = blockIdx.x * blockDim.x + threadIdx.x;
    if (i < PP * NN) {
        int c = i / NN, n = i % NN;
        pos[i] = rh[c * HH + n / HH] + rw[c * HH + n % HH];
    }
}

// ===========================================================================
// tf32 tensor-core GEMM: C[b][m][n] = sum_k W[m][k] * B[b][k][n], n<196.
//   W row-major [M,K] shared across batch; B per-batch [K,196].
//   MODE 0: plain   MODE 1: BN+ReLU   MODE 2: BN + residual + ReLU
// CTA tile 64(m) x 224(n; cols 196..223 zero-padded), BK=16, 256 threads
// = 8 warps arranged 2(m) x 4(n). Warp tile 32m x 56n = 2 A-frags x 7 B-frags
// of mma.m16n8k8. Double-buffered smem; tf32 conversion at STS time.
// Bank design: As[k][m] stride 72 (72%32==8), Bs[k][n] stride 232 (232%32==8)
// -> fragment LDS banks = tig*8+gid, conflict-free.
// ===========================================================================
template<int MODE>
__global__ void __launch_bounds__(256)
gemm_tf32_kernel(const float* __restrict__ W,
                 const float* __restrict__ B, size_t bStride,
                 float* __restrict__ C, size_t cStride,
                 int M, int K,
                 const float* __restrict__ gg, const float* __restrict__ bbeta,
                 const float* __restrict__ mmu, const float* __restrict__ vvar,
                 const float* __restrict__ res, size_t resStride)
{
    __shared__ unsigned As[2][16][72];    // [k][m], 64 used
    __shared__ unsigned Bs[2][16][232];   // [k][n], 224 used (196 real)

    const int batch = blockIdx.y;
    const int m0    = blockIdx.x * 64;
    const float* Bb = B + (size_t)batch * bStride;

    const int tid  = threadIdx.x;
    const int warp = tid >> 5;
    const int lane = tid & 31;
    const int mw   = warp >> 2;          // 0..1 : m offset mw*32
    const int nw   = warp & 3;           // 0..3 : n offset nw*56
    const int gid  = lane >> 2;          // 0..7
    const int tig  = lane & 3;           // 0..3

    float acc[2][7][4];
    #pragma unroll
    for (int i = 0; i < 2; i++)
        #pragma unroll
        for (int f = 0; f < 7; f++)
            #pragma unroll
            for (int c = 0; c < 4; c++) acc[i][f][c] = 0.f;

    auto load_tile = [&](int buf, int k0) {
        // A: 64 rows x 16 k, transposed into As[k][m]
        #pragma unroll
        for (int idx = tid; idx < 1024; idx += 256) {
            int r = idx >> 4, kk = idx & 15;
            As[buf][kk][r] = f2tf32(W[(size_t)(m0 + r) * K + (k0 + kk)]);
        }
        // B: 16 k-rows x 56 float4 (n4 >= 49 zero pad)
        for (int i = tid; i < 896; i += 256) {
            int kk = i / 56, n4 = i % 56;
            uint4 u = make_uint4(0u, 0u, 0u, 0u);
            if (n4 < 49) {
                float4 v = *(const float4*)(Bb + (size_t)(k0 + kk) * NN + n4 * 4);
                u.x = f2tf32(v.x); u.y = f2tf32(v.y);
                u.z = f2tf32(v.z); u.w = f2tf32(v.w);
            }
            *(uint4*)&Bs[buf][kk][n4 * 4] = u;
        }
    };

    auto compute_tile = [&](int buf) {
        #pragma unroll
        for (int ks = 0; ks < 2; ks++) {
            const int k = ks * 8;
            unsigned a[2][4];
            #pragma unroll
            for (int i = 0; i < 2; i++) {
                int mbase = mw * 32 + i * 16 + gid;
                a[i][0] = As[buf][k + tig][mbase];
                a[i][1] = As[buf][k + tig][mbase + 8];
                a[i][2] = As[buf][k + tig + 4][mbase];
                a[i][3] = As[buf][k + tig + 4][mbase + 8];
            }
            #pragma unroll
            for (int f = 0; f < 7; f++) {
                unsigned b[2];
                int nbase = nw * 56 + f * 8 + gid;
                b[0] = Bs[buf][k + tig][nbase];
                b[1] = Bs[buf][k + tig + 4][nbase];
                mma_tf32(acc[0][f], a[0], b);
                mma_tf32(acc[1][f], a[1], b);
            }
        }
    };

    load_tile(0, 0);
    __syncthreads();
    int cur = 0;
    for (int k0 = 16; k0 < K; k0 += 16) {
        load_tile(cur ^ 1, k0);
        compute_tile(cur);
        __syncthreads();
        cur ^= 1;
    }
    compute_tile(cur);

    // Epilogue. c0,c1 -> row m_lo cols (n, n+1); c2,c3 -> row m_lo+8.
    float* Cb = C + (size_t)batch * cStride;
    #pragma unroll
    for (int i = 0; i < 2; i++) {
        int m_lo = m0 + mw * 32 + i * 16 + gid;
        int m_hi = m_lo + 8;
        float s_lo = 1.f, t_lo = 0.f, s_hi = 1.f, t_hi = 0.f;
        if (MODE >= 1) {
            s_lo = gg[m_lo] * rsqrtf(vvar[m_lo] + 1e-5f);
            t_lo = bbeta[m_lo] - mmu[m_lo] * s_lo;
            s_hi = gg[m_hi] * rsqrtf(vvar[m_hi] + 1e-5f);
            t_hi = bbeta[m_hi] - mmu[m_hi] * s_hi;
        }
        #pragma unroll
        for (int f = 0; f < 7; f++) {
            int n = nw * 56 + f * 8 + tig * 2;
            if (n < NN) {   // n even, NN even -> n+1 < NN too
                float v0 = acc[i][f][0], v1 = acc[i][f][1];
                float w0 = acc[i][f][2], w1 = acc[i][f][3];
                if (MODE >= 1) {
                    v0 = v0 * s_lo + t_lo; v1 = v1 * s_lo + t_lo;
                    w0 = w0 * s_hi + t_hi; w1 = w1 * s_hi + t_hi;
                }
                if (MODE == 2) {
                    const float* rbl = res + (size_t)batch * resStride + (size_t)m_lo * NN;
                    const float* rbh = res + (size_t)batch * resStride + (size_t)m_hi * NN;
                    float2 r0 = *(const float2*)&rbl[n];
                    float2 r1 = *(const float2*)&rbh[n];
                    v0 += r0.x; v1 += r0.y; w0 += r1.x; w1 += r1.y;
                }
                if (MODE >= 1) {
                    v0 = fmaxf(v0, 0.f); v1 = fmaxf(v1, 0.f);
                    w0 = fmaxf(w0, 0.f); w1 = fmaxf(w1, 0.f);
                }
                float2 o0; o0.x = v0; o0.y = v1;
                float2 o1; o1.x = w0; o1.y = w1;
                *(float2*)&Cb[(size_t)m_lo * NN + n] = o0;
                *(float2*)&Cb[(size_t)m_hi * NN + n] = o1;
            }
        }
    }
}

// ---------------------------------------------------------------------------
// fp32 FFMA2 GEMM, kept for the AV stage (TRANS_B): aout = V @ Attn^T.
// BM=128 x 196, BK=16, 224 threads, per-thread 8x14, double-buffered.
// ---------------------------------------------------------------------------
template<int MODE, bool TRANS_B>
__global__ void __launch_bounds__(224)
gemm196_kernel(const float* __restrict__ A, size_t aStride,
               const float* __restrict__ B, size_t bStride,
               float* __restrict__ C, size_t cStride,
               int M, int K,
               const float* __restrict__ gg, const float* __restrict__ bbeta,
               const float* __restrict__ mmu, const float* __restrict__ vvar,
               const float* __restrict__ res, size_t resStride)
{
    __shared__ float2 As2[2][16][129];
    __shared__ float  Bs[2][16][196];

    const int batch = blockIdx.y;
    const int m0    = blockIdx.x * 128;
    const float* Ab = A + (size_t)batch * aStride;
    const float* Bb = B + (size_t)batch * bStride;

    const int tid = threadIdx.x;
    const int tx  = tid % 14;
    const int ty  = tid / 14;

    unsigned long long acc[8][7];
    #pragma unroll
    for (int i = 0; i < 8; i++)
        #pragma unroll
        for (int j = 0; j < 7; j++) acc[i][j] = 0ull;

    auto load_tile = [&](int buf, int k0) {
        for (int idx = tid; idx < 2048; idx += 224) {
            int r = idx >> 4, kk = idx & 15;
            int kc = k0 + kk;
            float a = (kc < K) ? Ab[(size_t)(m0 + r) * K + kc] : 0.f;
            As2[buf][kk][r] = make_float2(a, a);
        }
        if (!TRANS_B) {
            for (int i = tid; i < 784; i += 224) {
                int kk = i / 49, n4 = i % 49;
                int kc = k0 + kk;
                float4 v4 = make_float4(0.f, 0.f, 0.f, 0.f);
                if (kc < K) v4 = *(const float4*)(Bb + (size_t)kc * NN + n4 * 4);
                *(float4*)&Bs[buf][kk][n4 * 4] = v4;
            }
        } else {
            if (tid < NN) {
                const float* row = Bb + (size_t)tid * NN + k0;
                #pragma unroll
                for (int q4 = 0; q4 < 4; q4++) {
                    float4 v4;
                    int kc = k0 + q4 * 4;
                    if (kc + 3 < K) {
                        v4 = *(const float4*)(row + q4 * 4);
                    } else {
                        v4.x = (kc + 0 < K) ? row[q4 * 4 + 0] : 0.f;
                        v4.y = (kc + 1 < K) ? row[q4 * 4 + 1] : 0.f;
                        v4.z = (kc + 2 < K) ? row[q4 * 4 + 2] : 0.f;
                        v4.w = (kc + 3 < K) ? row[q4 * 4 + 3] : 0.f;
                    }
                    Bs[buf][q4 * 4 + 0][tid] = v4.x;
                    Bs[buf][q4 * 4 + 1][tid] = v4.y;
                    Bs[buf][q4 * 4 + 2][tid] = v4.z;
                    Bs[buf][q4 * 4 + 3][tid] = v4.w;
                }
            }
        }
    };

    auto compute_tile = [&](int buf) {
        #pragma unroll
        for (int kk = 0; kk < 16; kk++) {
            unsigned long long a2[8], b2[7];
            #pragma unroll
            for (int i = 0; i < 8; i++)
                a2[i] = *(const unsigned long long*)&As2[buf][kk][ty * 8 + i];
            #pragma unroll
            for (int j = 0; j < 7; j++)
                b2[j] = *(const unsigned long long*)&Bs[buf][kk][tx * 14 + 2 * j];
            #pragma unroll
            for (int i = 0; i < 8; i++)
                #pragma unroll
                for (int j = 0; j < 7; j++)
                    acc[i][j] = ffma2(a2[i], b2[j], acc[i][j]);
        }
    };

    load_tile(0, 0);
    __syncthreads();
    int cur = 0;
    for (int k0 = 16; k0 < K; k0 += 16) {
        load_tile(cur ^ 1, k0);
        compute_tile(cur);
        __syncthreads();
        cur ^= 1;
    }
    compute_tile(cur);

    float* Cb = C + (size_t)batch * cStride;
    #pragma unroll
    for (int i = 0; i < 8; i++) {
        int m = m0 + ty * 8 + i;
        float s = 1.f, t = 0.f;
        if (MODE >= 1) {
            s = gg[m] * rsqrtf(vvar[m] + 1e-5f);
            t = bbeta[m] - mmu[m] * s;
        }
        const float* rb = (MODE == 2)
            ? (res + (size_t)batch * resStride + (size_t)m * NN) : nullptr;
        #pragma unroll
        for (int j = 0; j < 7; j++) {
            int n = tx * 14 + 2 * j;
            float v0 = __uint_as_float((unsigned int)(acc[i][j]));
            float v1 = __uint_as_float((unsigned int)(acc[i][j] >> 32));
            if (MODE >= 1) { v0 = v0 * s + t; v1 = v1 * s + t; }
            if (MODE == 2) {
                float2 r2 = *(const float2*)&rb[n];
                v0 += r2.x; v1 += r2.y;
            }
            if (MODE >= 1) { v0 = fmaxf(v0, 0.f); v1 = fmaxf(v1, 0.f); }
            float2 o; o.x = v0; o.y = v1;
            *(float2*)&Cb[(size_t)m * NN + n] = o;
        }
    }
}

// ---------------------------------------------------------------------------
// Attention logits (fp32): L[b][n][m] = Q^T K + Pos^T Q, K=1024.
// ---------------------------------------------------------------------------
__global__ void __launch_bounds__(224, 2)
logits_kernel(const float* __restrict__ qkv, const float* __restrict__ pos,
              float* __restrict__ Lout)
{
    __shared__ float2 As2[2][16][65];
    __shared__ float  Bs[2][16][196];

    const int batch = blockIdx.y;
    const int n0    = blockIdx.x * 64;
    const float* qb = qkv + (size_t)batch * ((size_t)QKV3 * NN);
    const float* kb = qb + (size_t)PP * NN;

    const int tid = threadIdx.x;
    const int tx  = tid % 14, ty = tid / 14;

    unsigned long long acc[4][7];
    #pragma unroll
    for (int i = 0; i < 4; i++)
        #pragma unroll
        for (int j = 0; j < 7; j++) acc[i][j] = 0ull;

    auto load_tile = [&](int buf, int k0) {
        for (int idx = tid; idx < 1024; idx += 224) {
            int kk = idx >> 6, r = idx & 63;
            int kc = k0 + kk;
            const float* arow = (kc < PP) ? (qb + (size_t)kc * NN)
                                          : (pos + (size_t)(kc - PP) * NN);
            int n = n0 + r;
            float a = (n < NN) ? arow[n] : 0.f;
            As2[buf][kk][r] = make_float2(a, a);
        }
        for (int i = tid; i < 784; i += 224) {
            int kk = i / 49, n4 = i % 49;
            int kc = k0 + kk;
            const float* brow = (kc < PP) ? (kb + (size_t)kc * NN)
                                          : (qb + (size_t)(kc - PP) * NN);
            *(float4*)&Bs[buf][kk][n4 * 4] = *(const float4*)(brow + n4 * 4);
        }
    };

    auto compute_tile = [&](int buf) {
        #pragma unroll
        for (int kk = 0; kk < 16; kk++) {
            unsigned long long a2[4], b2[7];
            #pragma unroll
            for (int i = 0; i < 4; i++)
                a2[i] = *(const unsigned long long*)&As2[buf][kk][ty * 4 + i];
            #pragma unroll
            for (int j = 0; j < 7; j++)
                b2[j] = *(const unsigned long long*)&Bs[buf][kk][tx * 14 + 2 * j];
            #pragma unroll
            for (int i = 0; i < 4; i++)
                #pragma unroll
                for (int j = 0; j < 7; j++)
                    acc[i][j] = ffma2(a2[i], b2[j], acc[i][j]);
        }
    };

    load_tile(0, 0);
    __syncthreads();
    int cur = 0;
    for (int k0 = 16; k0 < 2 * PP; k0 += 16) {
        load_tile(cur ^ 1, k0);
        compute_tile(cur);
        __syncthreads();
        cur ^= 1;
    }
    compute_tile(cur);

    float* Lb = Lout + (size_t)batch * (NN * NN);
    #pragma unroll
    for (int i = 0; i < 4; i++) {
        int n = n0 + ty * 4 + i;
        if (n < NN) {
            #pragma unroll
            for (int j = 0; j < 7; j++) {
                int m = tx * 14 + 2 * j;
                float2 o;
                o.x = __uint_as_float((unsigned int)(acc[i][j]));
                o.y = __uint_as_float((unsigned int)(acc[i][j] >> 32));
                *(float2*)&Lb[(size_t)n * NN + m] = o;
            }
        }
    }
}

// ---------------------------------------------------------------------------
// In-place softmax over last dim (196). One warp per row; 7 elems/lane.
// ---------------------------------------------------------------------------
__global__ void softmax_kernel(float* __restrict__ L)
{
    int gw   = (blockIdx.x * blockDim.x + threadIdx.x) >> 5;
    int lane = threadIdx.x & 31;
    if (gw >= BB * NN) return;
    float* row = L + (size_t)gw * NN;

    float v[7];
    float mx = -1e30f;
    #pragma unroll
    for (int i = 0; i < 7; i++) {
        int m = lane + 32 * i;
        v[i] = (m < NN) ? row[m] : -1e30f;
        mx = fmaxf(mx, v[i]);
    }
    #pragma unroll
    for (int off = 16; off; off >>= 1)
        mx = fmaxf(mx, __shfl_xor_sync(0xffffffffu, mx, off));

    float sum = 0.f;
    #pragma unroll
    for (int i = 0; i < 7; i++) { v[i] = __expf(v[i] - mx); sum += v[i]; }
    #pragma unroll
    for (int off = 16; off; off >>= 1)
        sum += __shfl_xor_sync(0xffffffffu, sum, off);

    float inv = 1.f / sum;
    #pragma unroll
    for (int i = 0; i < 7; i++) {
        int m = lane + 32 * i;
        if (m < NN) row[m] = v[i] * inv;
    }
}

// ---------------------------------------------------------------------------
// Launch
// ---------------------------------------------------------------------------
extern "C" void kernel_launch(void* const* d_in, const int* in_sizes, int n_in,
                              void* d_out, int out_size)
{
    const float* x     = (const float*)d_in[0];
    const float* w1    = (const float*)d_in[1];
    const float* g1    = (const float*)d_in[2];
    const float* b1    = (const float*)d_in[3];
    const float* m1    = (const float*)d_in[4];
    const float* v1    = (const float*)d_in[5];
    const float* wqkv  = (const float*)d_in[6];
    const float* rel_h = (const float*)d_in[7];
    const float* rel_w = (const float*)d_in[8];
    const float* g2    = (const float*)d_in[9];
    const float* b2    = (const float*)d_in[10];
    const float* m2    = (const float*)d_in[11];
    const float* v2    = (const float*)d_in[12];
    const float* w3    = (const float*)d_in[13];
    const float* g3    = (const float*)d_in[14];
    const float* b3    = (const float*)d_in[15];
    const float* m3    = (const float*)d_in[16];
    const float* v3    = (const float*)d_in[17];
    float* out = (float*)d_out;

    float *p_out1, *p_qkv, *p_attn, *p_aout, *p_pos;
    cudaGetSymbolAddress((void**)&p_out1, g_out1);
    cudaGetSymbolAddress((void**)&p_qkv,  g_qkv);
    cudaGetSymbolAddress((void**)&p_attn, g_attn);
    cudaGetSymbolAddress((void**)&p_aout, g_aout);
    cudaGetSymbolAddress((void**)&p_pos,  g_pos);

    // pos[c][n] = rel_h + rel_w
    posprep_kernel<<<(PP * NN + 255) / 256, 256>>>(rel_h, rel_w, p_pos);

    // Stage 1 (tf32 TC): out1 = relu(bn1(w1 @ x))
    gemm_tf32_kernel<1><<<dim3(PP / 64, BB), 256>>>(
        w1, x, (size_t)CIN * NN, p_out1, (size_t)PP * NN,
        PP, CIN, g1, b1, m1, v1, nullptr, 0);

    // Stage 2 (tf32 TC): qkv = wqkv @ out1
    gemm_tf32_kernel<0><<<dim3(QKV3 / 64, BB), 256>>>(
        wqkv, p_out1, (size_t)PP * NN, p_qkv, (size_t)QKV3 * NN,
        QKV3, PP, nullptr, nullptr, nullptr, nullptr, nullptr, 0);

    // Stage 3 (fp32): logits = Q^T K + Pos^T Q
    logits_kernel<<<dim3(4, BB), 224>>>(p_qkv, p_pos, p_attn);

    // Stage 4: softmax over m
    softmax_kernel<<<(BB * NN) / 8, 256>>>(p_attn);

    // Stage 5 (fp32): aout = relu(bn2(V @ Attn^T))
    gemm196_kernel<1, true><<<dim3(PP / 128, BB), 224>>>(
        p_qkv + (size_t)2 * PP * NN, (size_t)QKV3 * NN,
        p_attn, (size_t)NN * NN, p_aout, (size_t)PP * NN,
        PP, NN, g2, b2, m2, v2, nullptr, 0);

    // Stage 6 (tf32 TC): out = relu(bn3(w3 @ aout) + x)
    gemm_tf32_kernel<2><<<dim3(COUT / 64, BB), 256>>>(
        w3, p_aout, (size_t)PP * NN, out, (size_t)COUT * NN,
        COUT, PP, g3, b3, m3, v3, x, (size_t)COUT * NN);
}